// round 4
// baseline (speedup 1.0000x reference)
#include <cuda_runtime.h>
#include <cstdint>

// Entmax (alpha=1.5) per row, B=2048 x N=32000 fp32.
// v4: each row split across a 2-CTA cluster; half-row register-resident in
// 512 threads x 8 float4. Filter at local_max-1 (valid: <= tau*), one DSMEM
// candidate exchange, symmetric warp-0 Newton in both CTAs. 2 CTAs/SM ->
// memory phases of co-resident CTAs overlap serial tails.

#define NC   32000
#define NH   (NC / 2)        // 16000 elems per CTA
#define NVH  (NH / 4)        // 4000 float4 per CTA
#define TPB  512
#define VPT  8               // 512*8 = 4096 slots >= 4000
#define CAP  1024
#define NEG  (-1e30f)

struct SmemBox {
    int   cnt;               // true candidate count (may exceed CAP)
    float lmax;              // local half max
    float vmax;              // max of rejected (<= lmax-1) elems
    float tauref;
    int   pcnt;  float pvmax; float plmax;   // peer copies
    int   bK; float bS; float bV;            // fallback broadcast
    int   fk[2]; float fS[2]; float fv[2];   // fallback mailboxes
    float red_f[16]; float red_g[16]; int red_i[16];
    float cand[2 * CAP];
};

__device__ __forceinline__ uint32_t smem_u32(const void* p) {
    uint32_t a;
    asm("{ .reg .u64 t; cvta.to.shared.u64 t, %1; cvt.u32.u64 %0, t; }"
        : "=r"(a) : "l"(p));
    return a;
}
__device__ __forceinline__ uint32_t mapa_rank(uint32_t addr, uint32_t rank) {
    uint32_t r;
    asm("mapa.shared::cluster.u32 %0, %1, %2;" : "=r"(r) : "r"(addr), "r"(rank));
    return r;
}
__device__ __forceinline__ float ld_dsmem_f32(uint32_t addr) {
    float v;
    asm volatile("ld.shared::cluster.f32 %0, [%1];" : "=f"(v) : "r"(addr));
    return v;
}
__device__ __forceinline__ int ld_dsmem_s32(uint32_t addr) {
    int v;
    asm volatile("ld.shared::cluster.s32 %0, [%1];" : "=r"(v) : "r"(addr));
    return v;
}
#define CLUSTER_SYNC() do { \
    asm volatile("barrier.cluster.arrive.aligned;" ::: "memory"); \
    asm volatile("barrier.cluster.wait.aligned;"   ::: "memory"); \
} while (0)

__global__ __launch_bounds__(TPB, 2) __cluster_dims__(2, 1, 1)
void entmax_kernel(const float* __restrict__ z, float* __restrict__ out) {
    __shared__ SmemBox s;

    const int tid  = threadIdx.x;
    const int lane = tid & 31;
    const int wid  = tid >> 5;
    const int rank = blockIdx.x & 1;          // == cluster ctarank
    const int row  = blockIdx.x >> 1;

    const long long base = (long long)row * NC + (long long)rank * NH;
    const float4* zr   = (const float4*)(z + base);
    float4*       orow = (float4*)(out + base);

    // ---- load half-row into registers, local max ----
    float4 r[VPT];
    float lmax = NEG;
    #pragma unroll
    for (int j = 0; j < VPT; ++j) {
        const int f = tid + j * TPB;
        if (f < NVH) {
            float4 v = zr[f];
            r[j] = v;
            lmax = fmaxf(lmax, fmaxf(fmaxf(v.x, v.y), fmaxf(v.z, v.w)));
        } else {
            r[j] = make_float4(NEG, NEG, NEG, NEG);
        }
    }
    #pragma unroll
    for (int o = 16; o; o >>= 1)
        lmax = fmaxf(lmax, __shfl_xor_sync(0xffffffffu, lmax, o));
    if (lane == 0) s.red_f[wid] = lmax;
    if (tid == 0) s.cnt = 0;
    __syncthreads();
    if (tid < 32) {
        float m = (tid < 16) ? s.red_f[tid] : NEG;
        #pragma unroll
        for (int o = 16; o; o >>= 1)
            m = fmaxf(m, __shfl_xor_sync(0xffffffffu, m, o));
        if (tid == 0) { s.lmax = m; }
    }
    __syncthreads();
    const float tlo = s.lmax - 1.0f;   // local filter threshold, <= tau*

    // ---- filter sweep: candidates z > tlo (pad NEG values fall to vmax,
    // harmlessly). ----
    float vmax = NEG;
    #pragma unroll
    for (int j = 0; j < VPT; ++j) {
        float c;
        c = r[j].x; if (c > tlo) { int p = atomicAdd(&s.cnt, 1); if (p < CAP) s.cand[p] = c; } else vmax = fmaxf(vmax, c);
        c = r[j].y; if (c > tlo) { int p = atomicAdd(&s.cnt, 1); if (p < CAP) s.cand[p] = c; } else vmax = fmaxf(vmax, c);
        c = r[j].z; if (c > tlo) { int p = atomicAdd(&s.cnt, 1); if (p < CAP) s.cand[p] = c; } else vmax = fmaxf(vmax, c);
        c = r[j].w; if (c > tlo) { int p = atomicAdd(&s.cnt, 1); if (p < CAP) s.cand[p] = c; } else vmax = fmaxf(vmax, c);
    }
    #pragma unroll
    for (int o = 16; o; o >>= 1)
        vmax = fmaxf(vmax, __shfl_xor_sync(0xffffffffu, vmax, o));
    if (lane == 0) s.red_g[wid] = vmax;
    __syncthreads();
    if (tid < 32) {
        float m = (tid < 16) ? s.red_g[tid] : NEG;
        #pragma unroll
        for (int o = 16; o; o >>= 1)
            m = fmaxf(m, __shfl_xor_sync(0xffffffffu, m, o));
        if (tid == 0) s.vmax = m;
    }
    __syncthreads();

    // ---- publish done; exchange with peer ----
    CLUSTER_SYNC();

    const uint32_t peer = rank ^ 1;
    if (tid == 0) {
        s.pcnt  = ld_dsmem_s32(mapa_rank(smem_u32(&s.cnt),  peer));
        s.pvmax = ld_dsmem_f32(mapa_rank(smem_u32(&s.vmax), peer));
        s.plmax = ld_dsmem_f32(mapa_rank(smem_u32(&s.lmax), peer));
    }
    __syncthreads();

    const int  cnt_l = s.cnt;
    const int  cnt_p = s.pcnt;
    float tau_ref;

    if (cnt_l <= CAP && cnt_p <= CAP) {
        // ---- fast path: warp 0 (both CTAs, symmetric) merges + Newton ----
        if (wid == 0) {
            const uint32_t pcand = mapa_rank(smem_u32(&s.cand[0]), peer);
            for (int i = lane; i < cnt_p; i += 32)
                s.cand[cnt_l + i] = ld_dsmem_f32(pcand + 4u * (uint32_t)i);
            __syncwarp();
            const int m = cnt_l + cnt_p;

            // global row max = max over merged candidates
            float cm = NEG;
            for (int i = lane; i < m; i += 32) cm = fmaxf(cm, s.cand[i]);
            #pragma unroll
            for (int o = 16; o; o >>= 1)
                cm = fmaxf(cm, __shfl_xor_sync(0xffffffffu, cm, o));

            float tl = cm - 1.0f;
            int   kp = -1;
            int   kF = 1; float SF = 0.0f; float vcF = NEG;
            for (int itr = 0; itr < 64; ++itr) {
                int k = 0; float S = 0.0f; float vc = NEG;
                for (int i = lane; i < m; i += 32) {
                    const float c = s.cand[i];
                    if (c > tl) { k++; S += c; } else vc = fmaxf(vc, c);
                }
                #pragma unroll
                for (int o = 16; o; o >>= 1) {
                    k += __shfl_xor_sync(0xffffffffu, k, o);
                    S += __shfl_xor_sync(0xffffffffu, S, o);
                    vc = fmaxf(vc, __shfl_xor_sync(0xffffffffu, vc, o));
                }
                kF = k; SF = S; vcF = vc;
                if (k == kp) break;                // support fixed point
                kp = k;
                tl = (S - 1.0f) / (float)k;
            }
            // reference quirk: cs[k_max] = S + max{z <= tau_final} (0 if none)
            const float vfin = fmaxf(vcF, fmaxf(s.vmax, s.pvmax));
            const float vt = (vfin > -1e29f) ? vfin : 0.0f;
            if (lane == 0) s.tauref = (SF + vt - 1.0f) / (float)kF;
        }
        __syncthreads();
        tau_ref = s.tauref;
    } else {
        // ---- fallback: symmetric iterative Newton, DSMEM mailboxes ----
        float tau = fmaxf(s.lmax, s.plmax) - 1.0f;
        int kprev = -1;
        tau_ref = 0.0f;
        const uint32_t pk = mapa_rank(smem_u32(&s.fk[0]), peer);
        const uint32_t pS = mapa_rank(smem_u32(&s.fS[0]), peer);
        const uint32_t pv = mapa_rank(smem_u32(&s.fv[0]), peer);
        for (int it = 0; it < 64; ++it) {
            int k = 0; float S = 0.0f; float v = NEG;
            #pragma unroll
            for (int j = 0; j < VPT; ++j) {
                float c;
                c = r[j].x; if (c > tau) { k++; S += c; } else v = fmaxf(v, c);
                c = r[j].y; if (c > tau) { k++; S += c; } else v = fmaxf(v, c);
                c = r[j].z; if (c > tau) { k++; S += c; } else v = fmaxf(v, c);
                c = r[j].w; if (c > tau) { k++; S += c; } else v = fmaxf(v, c);
            }
            #pragma unroll
            for (int o = 16; o; o >>= 1) {
                k += __shfl_xor_sync(0xffffffffu, k, o);
                S += __shfl_xor_sync(0xffffffffu, S, o);
                v  = fmaxf(v, __shfl_xor_sync(0xffffffffu, v, o));
            }
            if (lane == 0) { s.red_i[wid] = k; s.red_f[wid] = S; s.red_g[wid] = v; }
            __syncthreads();
            if (tid < 32) {
                int   kk = (tid < 16) ? s.red_i[tid] : 0;
                float SS = (tid < 16) ? s.red_f[tid] : 0.0f;
                float vv = (tid < 16) ? s.red_g[tid] : NEG;
                #pragma unroll
                for (int o = 16; o; o >>= 1) {
                    kk += __shfl_xor_sync(0xffffffffu, kk, o);
                    SS += __shfl_xor_sync(0xffffffffu, SS, o);
                    vv  = fmaxf(vv, __shfl_xor_sync(0xffffffffu, vv, o));
                }
                if (tid == 0) {
                    const int sl = it & 1;
                    s.fk[sl] = kk; s.fS[sl] = SS; s.fv[sl] = vv;
                }
            }
            __syncthreads();
            CLUSTER_SYNC();                    // partials visible both ways
            if (tid == 0) {
                const int sl = it & 1;
                const int   K  = s.fk[sl] + ld_dsmem_s32(pk + 4u * sl);
                const float Sa = s.fS[sl] + ld_dsmem_f32(pS + 4u * sl);
                const float Va = fmaxf(s.fv[sl], ld_dsmem_f32(pv + 4u * sl));
                s.bK = K; s.bS = Sa; s.bV = Va;
            }
            __syncthreads();
            const int   K  = s.bK;
            const float Sa = s.bS;
            const float Va = s.bV;
            if (K == kprev || it == 63) {
                const float vt = (Va > -1e29f) ? Va : 0.0f;
                tau_ref = (Sa + vt - 1.0f) / (float)K;
                break;
            }
            kprev = K;
            tau = (Sa - 1.0f) / (float)K;
        }
    }

    // ---- output: relu(z - tau_ref)^1.5 from registers ----
    #pragma unroll
    for (int j = 0; j < VPT; ++j) {
        const int f = tid + j * TPB;
        if (f < NVH) {
            const float4 v = r[j];
            float a = v.x - tau_ref;
            float b = v.y - tau_ref;
            float c = v.z - tau_ref;
            float d = v.w - tau_ref;
            float4 o;
            if (fmaxf(fmaxf(a, b), fmaxf(c, d)) > 0.0f) {
                a = fmaxf(a, 0.0f); b = fmaxf(b, 0.0f);
                c = fmaxf(c, 0.0f); d = fmaxf(d, 0.0f);
                o.x = a * sqrtf(a);
                o.y = b * sqrtf(b);
                o.z = c * sqrtf(c);
                o.w = d * sqrtf(d);
            } else {
                o.x = 0.0f; o.y = 0.0f; o.z = 0.0f; o.w = 0.0f;
            }
            __stcs(&orow[f], o);
        }
    }

    // peer may still be reading our smem candidates; don't exit before it's done
    CLUSTER_SYNC();
}

extern "C" void kernel_launch(void* const* d_in, const int* in_sizes, int n_in,
                              void* d_out, int out_size) {
    const float* z = (const float*)d_in[0];
    float* out = (float*)d_out;
    const int rows = in_sizes[0] / NC;
    entmax_kernel<<<rows * 2, TPB>>>(z, out);
}

// round 5
// speedup vs baseline: 1.4520x; 1.4520x over previous
#include <cuda_runtime.h>
#include <cstdint>

// Entmax (alpha=1.5) per row, B=2048 x N=32000 fp32.
// v5: persistent CTA per SM + TMA (cp.async.bulk) double-buffer.
//   While row r is processed from registers (max -> filter@rowmax-1 ->
//   warp-0 Newton -> stcs output), row r+1 streams into dynamic smem via
//   the TMA engine. Read stream is continuous; no wave-transition bubbles.

#define NC        32000
#define NV        (NC / 4)
#define TPB       1024
#define VPT       8
#define CAP       1024
#define NEG       (-1e30f)
#define ROW_BYTES (NC * 4)

__device__ __forceinline__ uint32_t smem_u32(const void* p) {
    uint32_t a;
    asm("{ .reg .u64 t; cvta.to.shared.u64 t, %1; cvt.u32.u64 %0, t; }"
        : "=r"(a) : "l"(p));
    return a;
}
__device__ __forceinline__ void mbar_init(uint32_t a, uint32_t cnt) {
    asm volatile("mbarrier.init.shared.b64 [%0], %1;" :: "r"(a), "r"(cnt) : "memory");
}
__device__ __forceinline__ void mbar_expect_tx(uint32_t a, uint32_t bytes) {
    asm volatile("mbarrier.arrive.expect_tx.shared.b64 _, [%0], %1;"
                 :: "r"(a), "r"(bytes) : "memory");
}
__device__ __forceinline__ void tma_bulk_g2s(uint32_t dst, const void* src,
                                             uint32_t bytes, uint32_t mbar) {
    asm volatile(
        "cp.async.bulk.shared::cta.global.mbarrier::complete_tx::bytes "
        "[%0], [%1], %2, [%3];"
        :: "r"(dst), "l"(src), "r"(bytes), "r"(mbar) : "memory");
}
#define MBAR_WAIT(mbar, parity) do { \
    asm volatile( \
        "{\n\t.reg .pred P1;\n\t" \
        "WAIT_LOOP_%=:\n\t" \
        "mbarrier.try_wait.parity.acquire.cta.shared::cta.b64 P1, [%0], %1, 0x989680;\n\t" \
        "@P1 bra.uni WAIT_DONE_%=;\n\t" \
        "bra.uni WAIT_LOOP_%=;\n\t" \
        "WAIT_DONE_%=:\n\t}" \
        :: "r"(mbar), "r"(parity) : "memory"); \
} while (0)

__global__ __launch_bounds__(TPB, 1)
void entmax_kernel(const float* __restrict__ z, float* __restrict__ out,
                   int rows, int gstride) {
    __shared__ float    s_f[32];
    __shared__ float    s_g[32];
    __shared__ int      s_i[32];
    __shared__ float    s_cand[CAP];
    __shared__ int      s_cnt;
    __shared__ float    s_tau0, s_vmax, s_tauref;
    __shared__ int      s_bK;
    __shared__ float    s_bS, s_bV;
    __shared__ uint64_t s_mbar;
    extern __shared__ float4 s_buf[];            // NV float4 = 125 KB

    const int tid  = threadIdx.x;
    const int lane = tid & 31;
    const int wid  = tid >> 5;

    const uint32_t mbar = smem_u32(&s_mbar);
    const uint32_t bufa = smem_u32(s_buf);
    if (tid == 0) mbar_init(mbar, 1);
    __syncthreads();

    // kick off first row's TMA
    const int r0 = blockIdx.x;
    if (r0 < rows && tid == 0) {
        mbar_expect_tx(mbar, ROW_BYTES);
        tma_bulk_g2s(bufa, z + (long long)r0 * NC, ROW_BYTES, mbar);
    }

    uint32_t phase = 0;
    for (int row = r0; row < rows; row += gstride) {
        // ---- wait for this row's data, copy smem -> regs (+ local max) ----
        MBAR_WAIT(mbar, phase);
        phase ^= 1;

        float4 r[VPT];
        float lmax = NEG;
        #pragma unroll
        for (int j = 0; j < VPT; ++j) {
            const int f = tid + j * TPB;
            if (f < NV) {
                float4 v = s_buf[f];
                r[j] = v;
                lmax = fmaxf(lmax, fmaxf(fmaxf(v.x, v.y), fmaxf(v.z, v.w)));
            } else {
                r[j] = make_float4(NEG, NEG, NEG, NEG);
            }
        }
        __syncthreads();        // all smem reads done before buffer reuse

        // ---- issue next row's TMA (overlaps all compute below) ----
        if (tid == 0) {
            asm volatile("fence.proxy.async.shared::cta;" ::: "memory");
            const int nxt = row + gstride;
            if (nxt < rows) {
                mbar_expect_tx(mbar, ROW_BYTES);
                tma_bulk_g2s(bufa, z + (long long)nxt * NC, ROW_BYTES, mbar);
            }
            s_cnt = 0;
        }

        // ---- block max reduce -> tau0 = rowmax - 1 ----
        #pragma unroll
        for (int o = 16; o; o >>= 1)
            lmax = fmaxf(lmax, __shfl_xor_sync(0xffffffffu, lmax, o));
        if (lane == 0) s_f[wid] = lmax;
        __syncthreads();        // also publishes s_cnt = 0
        if (tid < 32) {
            float m = s_f[tid];
            #pragma unroll
            for (int o = 16; o; o >>= 1)
                m = fmaxf(m, __shfl_xor_sync(0xffffffffu, m, o));
            if (tid == 0) s_tau0 = m - 1.0f;
        }
        __syncthreads();
        const float tau0 = s_tau0;

        // ---- filter: candidates z > tau0 (<= tau*, so support-complete) ----
        float vmax = NEG;
        #pragma unroll
        for (int j = 0; j < VPT; ++j) {
            float c;
            c = r[j].x; if (c > tau0) { int p = atomicAdd(&s_cnt, 1); if (p < CAP) s_cand[p] = c; } else vmax = fmaxf(vmax, c);
            c = r[j].y; if (c > tau0) { int p = atomicAdd(&s_cnt, 1); if (p < CAP) s_cand[p] = c; } else vmax = fmaxf(vmax, c);
            c = r[j].z; if (c > tau0) { int p = atomicAdd(&s_cnt, 1); if (p < CAP) s_cand[p] = c; } else vmax = fmaxf(vmax, c);
            c = r[j].w; if (c > tau0) { int p = atomicAdd(&s_cnt, 1); if (p < CAP) s_cand[p] = c; } else vmax = fmaxf(vmax, c);
        }
        #pragma unroll
        for (int o = 16; o; o >>= 1)
            vmax = fmaxf(vmax, __shfl_xor_sync(0xffffffffu, vmax, o));
        if (lane == 0) s_g[wid] = vmax;
        __syncthreads();
        if (tid < 32) {
            float m = s_g[tid];
            #pragma unroll
            for (int o = 16; o; o >>= 1)
                m = fmaxf(m, __shfl_xor_sync(0xffffffffu, m, o));
            if (tid == 0) s_vmax = m;
        }
        __syncthreads();
        const int cnt = s_cnt;
        float tau_ref;

        if (cnt <= CAP) {
            // ---- fast path: warp 0 Newton on the candidate set ----
            if (wid == 0) {
                float tl = tau0;
                int   kp = -1;
                int   kF = 1; float SF = 0.0f; float vcF = NEG;
                for (int itr = 0; itr < 64; ++itr) {
                    int k = 0; float S = 0.0f; float vc = NEG;
                    for (int i = lane; i < cnt; i += 32) {
                        const float c = s_cand[i];
                        if (c > tl) { k++; S += c; } else vc = fmaxf(vc, c);
                    }
                    #pragma unroll
                    for (int o = 16; o; o >>= 1) {
                        k += __shfl_xor_sync(0xffffffffu, k, o);
                        S += __shfl_xor_sync(0xffffffffu, S, o);
                        vc = fmaxf(vc, __shfl_xor_sync(0xffffffffu, vc, o));
                    }
                    kF = k; SF = S; vcF = vc;
                    if (k == kp) break;           // support fixed point
                    kp = k;
                    tl = (S - 1.0f) / (float)k;
                }
                // reference quirk: cs[k_max] = S + max{z <= tau_final}
                const float vfin = fmaxf(vcF, s_vmax);
                const float vt = (vfin > -1e29f) ? vfin : 0.0f;
                if (lane == 0) s_tauref = (SF + vt - 1.0f) / (float)kF;
            }
            __syncthreads();
            tau_ref = s_tauref;
        } else {
            // ---- fallback: block-wide Newton over register data ----
            float tau = tau0;
            int kprev = -1;
            tau_ref = 0.0f;
            for (int it = 0; it < 64; ++it) {
                int k = 0; float S = 0.0f; float v = NEG;
                #pragma unroll
                for (int j = 0; j < VPT; ++j) {
                    float c;
                    c = r[j].x; if (c > tau) { k++; S += c; } else v = fmaxf(v, c);
                    c = r[j].y; if (c > tau) { k++; S += c; } else v = fmaxf(v, c);
                    c = r[j].z; if (c > tau) { k++; S += c; } else v = fmaxf(v, c);
                    c = r[j].w; if (c > tau) { k++; S += c; } else v = fmaxf(v, c);
                }
                #pragma unroll
                for (int o = 16; o; o >>= 1) {
                    k += __shfl_xor_sync(0xffffffffu, k, o);
                    S += __shfl_xor_sync(0xffffffffu, S, o);
                    v  = fmaxf(v, __shfl_xor_sync(0xffffffffu, v, o));
                }
                if (lane == 0) { s_i[wid] = k; s_f[wid] = S; s_g[wid] = v; }
                __syncthreads();
                if (tid < 32) {
                    int kk = s_i[tid]; float SS = s_f[tid]; float vv = s_g[tid];
                    #pragma unroll
                    for (int o = 16; o; o >>= 1) {
                        kk += __shfl_xor_sync(0xffffffffu, kk, o);
                        SS += __shfl_xor_sync(0xffffffffu, SS, o);
                        vv  = fmaxf(vv, __shfl_xor_sync(0xffffffffu, vv, o));
                    }
                    if (tid == 0) { s_bK = kk; s_bS = SS; s_bV = vv; }
                }
                __syncthreads();
                const int   K  = s_bK;
                const float Sa = s_bS;
                const float Va = s_bV;
                if (K == kprev || it == 63) {
                    const float vt = (Va > -1e29f) ? Va : 0.0f;
                    tau_ref = (Sa + vt - 1.0f) / (float)K;
                    break;
                }
                kprev = K;
                tau = (Sa - 1.0f) / (float)K;
                __syncthreads();
            }
        }

        // ---- output: relu(z - tau_ref)^1.5 from registers ----
        float4* orow = (float4*)(out + (long long)row * NC);
        #pragma unroll
        for (int j = 0; j < VPT; ++j) {
            const int f = tid + j * TPB;
            if (f < NV) {
                const float4 v = r[j];
                float a = v.x - tau_ref;
                float b = v.y - tau_ref;
                float c = v.z - tau_ref;
                float d = v.w - tau_ref;
                float4 o;
                if (fmaxf(fmaxf(a, b), fmaxf(c, d)) > 0.0f) {
                    a = fmaxf(a, 0.0f); b = fmaxf(b, 0.0f);
                    c = fmaxf(c, 0.0f); d = fmaxf(d, 0.0f);
                    o.x = a * sqrtf(a);
                    o.y = b * sqrtf(b);
                    o.z = c * sqrtf(c);
                    o.w = d * sqrtf(d);
                } else {
                    o.x = 0.0f; o.y = 0.0f; o.z = 0.0f; o.w = 0.0f;
                }
                __stcs(&orow[f], o);
            }
        }
        // next iteration's MBAR_WAIT orders us behind the in-flight TMA;
        // s_cand/s_cnt reuse is protected by the barriers above.
    }
}

extern "C" void kernel_launch(void* const* d_in, const int* in_sizes, int n_in,
                              void* d_out, int out_size) {
    const float* z = (const float*)d_in[0];
    float* out = (float*)d_out;
    const int rows = in_sizes[0] / NC;

    int dev = 0, sms = 148;
    cudaGetDevice(&dev);
    cudaDeviceGetAttribute(&sms, cudaDevAttrMultiProcessorCount, dev);
    cudaFuncSetAttribute(entmax_kernel,
                         cudaFuncAttributeMaxDynamicSharedMemorySize, ROW_BYTES);

    const int grid = (rows < sms) ? rows : sms;
    entmax_kernel<<<grid, TPB, ROW_BYTES>>>(z, out, rows, grid);
}